// round 11
// baseline (speedup 1.0000x reference)
#include <cuda_runtime.h>
#include <math.h>
#include <stdint.h>

#define T 2048
#define D 768
#define NH 12
#define DH 64
#define D3 2304
#define D4 3072

// packed projection layout
#define NB     3276
#define C_QKV  0
#define C_GEOV 2304
#define C_W1   3072
#define C_W2   3120
#define C_R1   3168
#define C_R2   3216
#define C_GATE 3264

// ---------------- scratch (static device globals; no allocation) ----------------
__device__ float g_ln1[T * D];
__device__ float g_big[T * NB];
__device__ float g_bigw[D * NB];
__device__ float g_bigb[NB];
__device__ float g_fcw[D * D4];
__device__ float g_projw[D4 * D];
__device__ float g_outw[D * D];
__device__ float g_jw[T * NH * 6];
__device__ float g_rd[T * NH * 6];
__device__ float g_gate[T];
__device__ float g_pstd[T * D];
__device__ float g_pgeo[T * D];
__device__ float g_comb[T * D];
__device__ float g_res[T * D];
__device__ float g_m[T * D];
__device__ float g_fc[T * D4];

__device__ __forceinline__ float gelu_f(float v) {
    const float c = 0.7978845608028654f;
    float u = c * (v + 0.044715f * v * v * v);
    return 0.5f * v * (1.0f + tanhf(u));
}

__device__ __forceinline__ uint32_t f2tf32(float x) {
    uint32_t r;
    asm("cvt.rna.tf32.f32 %0, %1;" : "=r"(r) : "f"(x));
    return r;
}
__device__ __forceinline__ float tf32bits(float x) {
    return __uint_as_float(f2tf32(x));
}

__device__ __forceinline__ void mma_tf32(float c[4], const uint32_t a[4], const uint32_t b[2]) {
    asm volatile(
        "mma.sync.aligned.m16n8k8.row.col.f32.tf32.tf32.f32 "
        "{%0,%1,%2,%3},{%4,%5,%6,%7},{%8,%9},{%0,%1,%2,%3};"
        : "+f"(c[0]), "+f"(c[1]), "+f"(c[2]), "+f"(c[3])
        : "r"(a[0]), "r"(a[1]), "r"(a[2]), "r"(a[3]), "r"(b[0]), "r"(b[1]));
}

__device__ __forceinline__ void cpa16(void* dst, const void* src, bool pred) {
    uint32_t d = (uint32_t)__cvta_generic_to_shared(dst);
    int sz = pred ? 16 : 0;
    asm volatile("cp.async.ca.shared.global [%0], [%1], 16, %2;"
                 :: "r"(d), "l"(src), "r"(sz));
}
#define CP_COMMIT() asm volatile("cp.async.commit_group;")
#define CP_WAIT1()  asm volatile("cp.async.wait_group 1;" ::: "memory")

// ---------------- pipelined tf32 GEMM: 128 threads, 4 warps, big warp tiles ----------------
// CFG 0: 128x128 CTA tile, warps 2x2 of 64x64 (MI=4, NI=8)
// CFG 1:  64x128 CTA tile, warps 2x2 of 32x64 (MI=2, NI=8)
template<int CFG>
__global__ void __launch_bounds__(128)
gemm_pl_k(const float* __restrict__ A, int lda,
          const float* __restrict__ B, int ldb,
          float* __restrict__ C, int ldc,
          const float* __restrict__ bias,
          const float* __restrict__ resid,
          int M, int N, int K, int act, int roundOut)
{
    constexpr int BMt = CFG ? 64 : 128;
    constexpr int MI  = CFG ? 2 : 4;

    const int bm0 = blockIdx.y * BMt, bn0 = blockIdx.x * 128;

    __shared__ float As[2][BMt][20];
    __shared__ float Bs[2][16][132];

    const int tid = threadIdx.x, lane = tid & 31, wid = tid >> 5;
    const int wm = (wid & 1) * (BMt / 2);
    const int wn = (wid >> 1) * 64;
    const int grp = lane >> 2, qid = lane & 3;

    float acc[MI][8][4];
#pragma unroll
    for (int mi = 0; mi < MI; mi++)
#pragma unroll
        for (int ni = 0; ni < 8; ni++)
#pragma unroll
            for (int r = 0; r < 4; r++) acc[mi][ni][r] = 0.f;

    auto prefetch = [&](int pb, int k0) {
#pragma unroll
        for (int i = tid; i < BMt * 4; i += 128) {
            int row = i >> 2, kq = i & 3;
            cpa16(&As[pb][row][kq * 4],
                  &A[(size_t)(bm0 + row) * lda + k0 + kq * 4], true);
        }
#pragma unroll
        for (int i = tid; i < 512; i += 128) {
            int k = i >> 5, nq = i & 31;
            int gn = bn0 + nq * 4;
            cpa16(&Bs[pb][k][nq * 4],
                  &B[(size_t)(k0 + k) * ldb + gn], gn < N);
        }
    };

    prefetch(0, 0);
    CP_COMMIT();
    int buf = 0;
    for (int k0 = 0; k0 < K; k0 += 16) {
        if (k0 + 16 < K) prefetch(buf ^ 1, k0 + 16);
        CP_COMMIT();
        CP_WAIT1();
        __syncthreads();
#pragma unroll
        for (int ks = 0; ks < 16; ks += 8) {
            uint32_t af[MI][4];
#pragma unroll
            for (int mi = 0; mi < MI; mi++) {
                int m0 = wm + mi * 16;
                af[mi][0] = __float_as_uint(As[buf][m0 + grp][ks + qid]);
                af[mi][1] = __float_as_uint(As[buf][m0 + grp + 8][ks + qid]);
                af[mi][2] = __float_as_uint(As[buf][m0 + grp][ks + qid + 4]);
                af[mi][3] = __float_as_uint(As[buf][m0 + grp + 8][ks + qid + 4]);
            }
#pragma unroll
            for (int ni = 0; ni < 8; ni++) {
                int n0 = wn + ni * 8;
                uint32_t bf[2];
                bf[0] = __float_as_uint(Bs[buf][ks + qid][n0 + grp]);
                bf[1] = __float_as_uint(Bs[buf][ks + qid + 4][n0 + grp]);
#pragma unroll
                for (int mi = 0; mi < MI; mi++)
                    mma_tf32(acc[mi][ni], af[mi], bf);
            }
        }
        __syncthreads();
        buf ^= 1;
    }

#pragma unroll
    for (int mi = 0; mi < MI; mi++) {
#pragma unroll
        for (int ni = 0; ni < 8; ni++) {
            int colb = bn0 + wn + ni * 8 + qid * 2;
#pragma unroll
            for (int r = 0; r < 2; r++) {
                int row = bm0 + wm + mi * 16 + grp + r * 8;
#pragma unroll
                for (int cs = 0; cs < 2; cs++) {
                    int c = colb + cs;
                    if (c >= N) continue;
                    float v = acc[mi][ni][r * 2 + cs];
                    if (bias) v += bias[c];
                    if (act) v = gelu_f(v);
                    if (resid) v += resid[(size_t)row * ldc + c];
                    if (roundOut) v = tf32bits(v);
                    C[(size_t)row * ldc + c] = v;
                }
            }
        }
    }
}

// ---------------- weight/bias pack (bigw stored tf32-rounded) ----------------
__global__ void pack_k(const float* __restrict__ qkv_w, const float* __restrict__ geov_w,
                       const float* __restrict__ w1w, const float* __restrict__ w2w,
                       const float* __restrict__ w1r, const float* __restrict__ w2r,
                       const float* __restrict__ gate_w,
                       const float* __restrict__ qkv_b, const float* __restrict__ geov_b,
                       const float* __restrict__ gate_b,
                       float* __restrict__ bigw, float* __restrict__ bigb)
{
    int col = blockIdx.x * 256 + threadIdx.x;
    int k = blockIdx.y;
    if (col >= NB) return;
    float v;
    if      (col < C_GEOV) v = qkv_w[(size_t)k * D3 + col];
    else if (col < C_W1)   v = geov_w[(size_t)k * D + (col - C_GEOV)];
    else if (col < C_W2)   v = w1w[(size_t)k * 48 + (col - C_W1)];
    else if (col < C_R1)   v = w2w[(size_t)k * 48 + (col - C_W2)];
    else if (col < C_R2)   v = w1r[(size_t)k * 48 + (col - C_R1)];
    else if (col < C_GATE) v = w2r[(size_t)k * 48 + (col - C_R2)];
    else                   v = gate_w[(size_t)k * NH + (col - C_GATE)];
    bigw[(size_t)k * NB + col] = tf32bits(v);
    if (k == 0) {
        float b;
        if      (col < C_GEOV) b = qkv_b[col];
        else if (col < C_W1)   b = geov_b[col - C_GEOV];
        else if (col < C_GATE) b = 0.f;
        else                   b = gate_b[col - C_GATE];
        bigb[col] = b;
    }
}

// ---------------- weight converts: fc/proj/out rounded copies ----------------
__global__ void convw_k(const float* __restrict__ fw, const float* __restrict__ pw,
                        const float* __restrict__ ow,
                        float* __restrict__ gfw, float* __restrict__ gpw,
                        float* __restrict__ gow)
{
    int i = blockIdx.x * 256 + threadIdx.x;
    if (i < D * D4) {
        gfw[i] = tf32bits(fw[i]);
        gpw[i] = tf32bits(pw[i]);
    }
    if (i < D * D) gow[i] = tf32bits(ow[i]);
}

// ---------------- flash attention body (R9/R10, unchanged) ----------------
template<int KD, int KLEN>
__device__ __forceinline__ void flash_body(
    const float* __restrict__ Qb, int qrs, int qhs,
    const float* __restrict__ Kb, int krs, int khs,
    const float* __restrict__ Vb, int vrs, int vhs,
    const float* __restrict__ scaleArr, float cscale,
    float* __restrict__ Ob,
    float* __restrict__ bufm, float* __restrict__ Vsm)
{
#define BUF(r, c) bufm[(r) * 68 + (c)]
#define VSM(r, c) Vsm[(r) * 68 + (c)]
    const int qb = gridDim.x - 1 - (int)blockIdx.x;   // LPT: heaviest first
    const int h = blockIdx.y;
    const int q0 = qb * 64;
    const int tid = threadIdx.x, lane = tid & 31, w = tid >> 5;
    const int grp = lane >> 2, qid = lane & 3;
    const int wm = w * 16;

    const float scale = scaleArr ? scaleArr[h] : cscale;

    if (KD == 64) {
        for (int i = tid; i < 64 * 16; i += 128) {
            int r = i >> 4, c4 = (i & 15) * 4;
            float4 v = *(const float4*)&Qb[(size_t)(q0 + r) * qrs + h * qhs + c4];
            BUF(r, c4)     = tf32bits(v.x);
            BUF(r, c4 + 1) = tf32bits(v.y);
            BUF(r, c4 + 2) = tf32bits(v.z);
            BUF(r, c4 + 3) = tf32bits(v.w);
        }
    } else {
        for (int i = tid; i < 64 * KD; i += 128) {
            int r = i / KD, c = i % KD;
            float v = (c < KLEN) ? Qb[(size_t)(q0 + r) * qrs + h * qhs + c] : 0.f;
            BUF(r, c) = tf32bits(v);
        }
    }
    __syncthreads();

    uint32_t qf[KD / 8][4];
#pragma unroll
    for (int s = 0; s < KD / 8; s++) {
        int ks = s * 8;
        qf[s][0] = __float_as_uint(BUF(wm + grp, ks + qid));
        qf[s][1] = __float_as_uint(BUF(wm + grp + 8, ks + qid));
        qf[s][2] = __float_as_uint(BUF(wm + grp, ks + qid + 4));
        qf[s][3] = __float_as_uint(BUF(wm + grp + 8, ks + qid + 4));
    }

    float m0 = -1e30f, m1 = -1e30f, l0 = 0.f, l1 = 0.f;
    float oacc[8][4] = {};
    const int rowg0 = q0 + wm + grp, rowg1 = rowg0 + 8;
    const int nkb = qb + 1;

    for (int kb = 0; kb < nkb; kb++) {
        const int s0 = kb * 64;
        __syncthreads();
        if (KD == 64) {
            for (int i = tid; i < 64 * 16; i += 128) {
                int r = i >> 4, c4 = (i & 15) * 4;
                float4 v = *(const float4*)&Kb[(size_t)(s0 + r) * krs + h * khs + c4];
                BUF(r, c4)     = tf32bits(v.x);
                BUF(r, c4 + 1) = tf32bits(v.y);
                BUF(r, c4 + 2) = tf32bits(v.z);
                BUF(r, c4 + 3) = tf32bits(v.w);
            }
        } else {
            for (int i = tid; i < 64 * KD; i += 128) {
                int r = i / KD, c = i % KD;
                float v = (c < KLEN) ? Kb[(size_t)(s0 + r) * krs + h * khs + c] : 0.f;
                BUF(r, c) = tf32bits(v);
            }
        }
        for (int i = tid; i < 64 * 16; i += 128) {
            int r = i >> 4, c4 = (i & 15) * 4;
            float4 v = *(const float4*)&Vb[(size_t)(s0 + r) * vrs + h * vhs + c4];
            VSM(r, c4)     = tf32bits(v.x);
            VSM(r, c4 + 1) = tf32bits(v.y);
            VSM(r, c4 + 2) = tf32bits(v.z);
            VSM(r, c4 + 3) = tf32bits(v.w);
        }
        __syncthreads();

        float sacc[8][4] = {};
#pragma unroll
        for (int s = 0; s < KD / 8; s++) {
            int ks = s * 8;
#pragma unroll
            for (int ni = 0; ni < 8; ni++) {
                uint32_t bf[2];
                bf[0] = __float_as_uint(BUF(ni * 8 + grp, ks + qid));
                bf[1] = __float_as_uint(BUF(ni * 8 + grp, ks + qid + 4));
                mma_tf32(sacc[ni], qf[s], bf);
            }
        }

        const bool dMask = (kb == nkb - 1);
#pragma unroll
        for (int ni = 0; ni < 8; ni++)
#pragma unroll
            for (int e = 0; e < 4; e++) {
                float v = sacc[ni][e] * scale;
                if (dMask) {
                    int col = s0 + ni * 8 + qid * 2 + (e & 1);
                    int row = (e < 2) ? rowg0 : rowg1;
                    if (col > row) v = -1e30f;
                }
                sacc[ni][e] = v;
            }

        float tm0 = -1e30f, tm1 = -1e30f;
#pragma unroll
        for (int ni = 0; ni < 8; ni++) {
            tm0 = fmaxf(tm0, fmaxf(sacc[ni][0], sacc[ni][1]));
            tm1 = fmaxf(tm1, fmaxf(sacc[ni][2], sacc[ni][3]));
        }
        tm0 = fmaxf(tm0, __shfl_xor_sync(0xffffffff, tm0, 1));
        tm0 = fmaxf(tm0, __shfl_xor_sync(0xffffffff, tm0, 2));
        tm1 = fmaxf(tm1, __shfl_xor_sync(0xffffffff, tm1, 1));
        tm1 = fmaxf(tm1, __shfl_xor_sync(0xffffffff, tm1, 2));

        const float mn0 = fmaxf(m0, tm0), mn1 = fmaxf(m1, tm1);
        const float a0 = __expf(m0 - mn0), a1 = __expf(m1 - mn1);
        m0 = mn0; m1 = mn1;

        float rs0 = 0.f, rs1 = 0.f;
#pragma unroll
        for (int ni = 0; ni < 8; ni++) {
            float p0 = __expf(sacc[ni][0] - mn0);
            float p1 = __expf(sacc[ni][1] - mn0);
            float p2 = __expf(sacc[ni][2] - mn1);
            float p3 = __expf(sacc[ni][3] - mn1);
            sacc[ni][0] = p0; sacc[ni][1] = p1; sacc[ni][2] = p2; sacc[ni][3] = p3;
            rs0 += p0 + p1; rs1 += p2 + p3;
        }
        rs0 += __shfl_xor_sync(0xffffffff, rs0, 1);
        rs0 += __shfl_xor_sync(0xffffffff, rs0, 2);
        rs1 += __shfl_xor_sync(0xffffffff, rs1, 1);
        rs1 += __shfl_xor_sync(0xffffffff, rs1, 2);
        l0 = l0 * a0 + rs0;
        l1 = l1 * a1 + rs1;

#pragma unroll
        for (int ni = 0; ni < 8; ni++) {
            oacc[ni][0] *= a0; oacc[ni][1] *= a0;
            oacc[ni][2] *= a1; oacc[ni][3] *= a1;
        }

        __syncthreads();
#pragma unroll
        for (int ni = 0; ni < 8; ni++) {
            int c = ni * 8 + qid * 2;
            BUF(wm + grp, c)         = tf32bits(sacc[ni][0]);
            BUF(wm + grp, c + 1)     = tf32bits(sacc[ni][1]);
            BUF(wm + grp + 8, c)     = tf32bits(sacc[ni][2]);
            BUF(wm + grp + 8, c + 1) = tf32bits(sacc[ni][3]);
        }
        __syncwarp();

#pragma unroll
        for (int ks = 0; ks < 64; ks += 8) {
            uint32_t af[4];
            af[0] = __float_as_uint(BUF(wm + grp, ks + qid));
            af[1] = __float_as_uint(BUF(wm + grp + 8, ks + qid));
            af[2] = __float_as_uint(BUF(wm + grp, ks + qid + 4));
            af[3] = __float_as_uint(BUF(wm + grp + 8, ks + qid + 4));
#pragma unroll
            for (int ni = 0; ni < 8; ni++) {
                uint32_t bf[2];
                bf[0] = __float_as_uint(VSM(ks + qid, ni * 8 + grp));
                bf[1] = __float_as_uint(VSM(ks + qid + 4, ni * 8 + grp));
                mma_tf32(oacc[ni], af, bf);
            }
        }
        __syncwarp();
    }

    const float inv0 = 1.f / l0, inv1 = 1.f / l1;
#pragma unroll
    for (int ni = 0; ni < 8; ni++) {
        int c = ni * 8 + qid * 2;
        Ob[(size_t)rowg0 * D + h * DH + c]     = oacc[ni][0] * inv0;
        Ob[(size_t)rowg0 * D + h * DH + c + 1] = oacc[ni][1] * inv0;
        Ob[(size_t)rowg1 * D + h * DH + c]     = oacc[ni][2] * inv1;
        Ob[(size_t)rowg1 * D + h * DH + c + 1] = oacc[ni][3] * inv1;
    }
#undef BUF
#undef VSM
}

// ---------------- merged std+geo flash ----------------
__global__ void flash_dual_k(const float* __restrict__ big,
                             const float* __restrict__ rd,
                             const float* __restrict__ jw,
                             const float* __restrict__ inc,
                             float* __restrict__ pstd,
                             float* __restrict__ pgeo)
{
    __shared__ float buf[64 * 68];
    __shared__ float Vs[64 * 68];
    if (blockIdx.z == 0) {
        flash_body<64, 64>(big + C_QKV, NB, DH,
                           big + C_QKV + D, NB, DH,
                           big + C_QKV + 2 * D, NB, DH,
                           nullptr, 0.125f, pstd, buf, Vs);
    } else {
        flash_body<8, 6>(rd, NH * 6, 6, jw, NH * 6, 6,
                         big + C_GEOV, NB, DH,
                         inc, 0.f, pgeo, buf, Vs);
    }
}

// ---------------- layernorm (optional tf32-rounded output) ----------------
__global__ void layernorm_k(const float* __restrict__ x, const float* __restrict__ g,
                            const float* __restrict__ b, float* __restrict__ y,
                            int roundOut)
{
    int t = blockIdx.x;
    const float* row = x + (size_t)t * D;
    __shared__ float sh[256];
    int tid = threadIdx.x;
    float s = 0.f;
    for (int i = tid; i < D; i += 256) s += row[i];
    sh[tid] = s; __syncthreads();
    for (int st = 128; st > 0; st >>= 1) { if (tid < st) sh[tid] += sh[tid + st]; __syncthreads(); }
    float mean = sh[0] / D;
    __syncthreads();
    float v = 0.f;
    for (int i = tid; i < D; i += 256) { float d = row[i] - mean; v += d * d; }
    sh[tid] = v; __syncthreads();
    for (int st = 128; st > 0; st >>= 1) { if (tid < st) sh[tid] += sh[tid + st]; __syncthreads(); }
    float rstd = rsqrtf(sh[0] / D + 1e-5f);
    for (int i = tid; i < D; i += 256) {
        float o = (row[i] - mean) * rstd * g[i] + b[i];
        y[(size_t)t * D + i] = roundOut ? tf32bits(o) : o;
    }
}

// ---------------- Plucker exterior + J6 + gate (merged) ----------------
__device__ __forceinline__ void exterior6(const float* a, const float* b, float* L)
{
    L[0] = a[0] * b[1] - a[1] * b[0];
    L[1] = a[0] * b[2] - a[2] * b[0];
    L[2] = a[0] * b[3] - a[3] * b[0];
    L[3] = a[1] * b[2] - a[2] * b[1];
    L[4] = a[1] * b[3] - a[3] * b[1];
    L[5] = a[2] * b[3] - a[3] * b[2];
    float n = sqrtf(L[0]*L[0] + L[1]*L[1] + L[2]*L[2] + L[3]*L[3] + L[4]*L[4] + L[5]*L[5]);
    float inv = 1.0f / fmaxf(n, 1e-12f);
#pragma unroll
    for (int i = 0; i < 6; i++) L[i] *= inv;
}

__global__ void linesgate_k(const float* __restrict__ big,
                            float* __restrict__ jw, float* __restrict__ rd,
                            float* __restrict__ gate)
{
    int idx = blockIdx.x * blockDim.x + threadIdx.x;
    if (idx < T) {
        const float* row = big + (size_t)idx * NB + C_GATE;
        float s = 0.f;
#pragma unroll
        for (int h = 0; h < NH; h++) s += 1.f / (1.f + __expf(-row[h]));
        gate[idx] = s / NH;
    }
    if (idx >= T * NH) return;
    int t = idx / NH, h = idx % NH;
    float a[4], b[4], L[6];
#pragma unroll
    for (int j = 0; j < 4; j++)
        a[j] = (t > 0) ? big[(size_t)(t - 1) * NB + C_W1 + h * 4 + j] : 0.f;
#pragma unroll
    for (int j = 0; j < 4; j++) b[j] = big[(size_t)t * NB + C_W2 + h * 4 + j];
    exterior6(a, b, L);
    float* o = jw + (size_t)idx * 6;
    o[0] =  L[5]; o[1] = -L[4]; o[2] =  L[3];
    o[3] =  L[2]; o[4] = -L[1]; o[5] =  L[0];
#pragma unroll
    for (int j = 0; j < 4; j++) a[j] = big[(size_t)t * NB + C_R1 + h * 4 + j];
#pragma unroll
    for (int j = 0; j < 4; j++) b[j] = big[(size_t)t * NB + C_R2 + h * 4 + j];
    exterior6(a, b, L);
    float* p = rd + (size_t)idx * 6;
#pragma unroll
    for (int i = 0; i < 6; i++) p[i] = L[i];
}

// ---------------- combine gate (tf32-rounded output; feeds out-proj A) ----------------
__global__ void combine_k(const float* __restrict__ so, const float* __restrict__ go,
                          const float* __restrict__ gate, float* __restrict__ out)
{
    int idx = blockIdx.x * 256 + threadIdx.x;
    if (idx >= T * D) return;
    float g = gate[idx / D];
    out[idx] = tf32bits((1.f - g) * so[idx] + g * go[idx]);
}

// ---------------- host launch ----------------
static float* symAddr(const void* sym)
{
    void* p = nullptr;
    cudaGetSymbolAddress(&p, sym);
    return (float*)p;
}

extern "C" void kernel_launch(void* const* d_in, const int* in_sizes, int n_in,
                              void* d_out, int out_size)
{
    const float* x       = (const float*)d_in[0];
    const float* ln1_g   = (const float*)d_in[1];
    const float* ln1_b   = (const float*)d_in[2];
    const float* qkv_w   = (const float*)d_in[3];
    const float* qkv_b   = (const float*)d_in[4];
    const float* w1w     = (const float*)d_in[5];
    const float* w2w     = (const float*)d_in[6];
    const float* w1r     = (const float*)d_in[7];
    const float* w2r     = (const float*)d_in[8];
    const float* geov_w  = (const float*)d_in[9];
    const float* geov_b  = (const float*)d_in[10];
    const float* gate_w  = (const float*)d_in[11];
    const float* gate_b  = (const float*)d_in[12];
    const float* inc     = (const float*)d_in[13];
    const float* out_w   = (const float*)d_in[14];
    const float* out_b   = (const float*)d_in[15];
    const float* ln2_g   = (const float*)d_in[16];
    const float* ln2_b   = (const float*)d_in[17];
    const float* fc_w    = (const float*)d_in[18];
    const float* fc_b    = (const float*)d_in[19];
    const float* proj_w  = (const float*)d_in[20];
    const float* proj_b  = (const float*)d_in[21];
    float* out = (float*)d_out;

    float* ln1   = symAddr(g_ln1);
    float* big   = symAddr(g_big);
    float* bigw  = symAddr(g_bigw);
    float* bigb  = symAddr(g_bigb);
    float* fcw   = symAddr(g_fcw);
    float* projw = symAddr(g_projw);
    float* outw  = symAddr(g_outw);
    float* jw    = symAddr(g_jw);
    float* rd    = symAddr(g_rd);
    float* gate  = symAddr(g_gate);
    float* pstd  = symAddr(g_pstd);
    float* pgeo  = symAddr(g_pgeo);
    float* comb  = symAddr(g_comb);
    float* res   = symAddr(g_res);
    float* mbuf  = symAddr(g_m);
    float* fcb   = symAddr(g_fc);

    // 1. pack weights (tf32) + biases; convert fc/proj/out weights
    pack_k<<<dim3((NB + 255) / 256, D), 256>>>(qkv_w, geov_w, w1w, w2w, w1r, w2r, gate_w,
                                               qkv_b, geov_b, gate_b, bigw, bigb);
    convw_k<<<(D * D4 + 255) / 256, 256>>>(fc_w, proj_w, out_w, fcw, projw, outw);

    // 2. ln1 (tf32-rounded; feeds mega-GEMM A)
    layernorm_k<<<T, 256>>>(x, ln1_g, ln1_b, ln1, 1);

    // 3. mega-GEMM: big = ln1 @ bigw + bigb
    gemm_pl_k<0><<<dim3((NB + 127) / 128, T / 128), 128>>>(ln1, D, bigw, NB, big, NB,
                                                           bigb, nullptr, T, NB, D, 0, 0);

    // 4. exterior + J6 + gate
    linesgate_k<<<(T * NH + 255) / 256, 256>>>(big, jw, rd, gate);

    // 5. merged std + geo flash attention
    flash_dual_k<<<dim3(T / 64, NH, 2), 128>>>(big, rd, jw, inc, pstd, pgeo);

    // 6. combine (rounded; feeds out-proj A)
    combine_k<<<(T * D + 255) / 256, 256>>>(pstd, pgeo, gate, comb);

    // 7. out proj + residual (res stays fp32)
    gemm_pl_k<1><<<dim3(D / 128, T / 64), 128>>>(comb, D, outw, D, res, D,
                                                 out_b, x, T, D, D, 0, 0);

    // 8. ln2 (rounded; feeds fc A)
    layernorm_k<<<T, 256>>>(res, ln2_g, ln2_b, mbuf, 1);

    // 9. fc + gelu (rounded output; feeds proj A)
    gemm_pl_k<0><<<dim3(D4 / 128, T / 128), 128>>>(mbuf, D, fcw, D4, fcb, D4,
                                                   fc_b, nullptr, T, D4, D, 1, 1);

    // 10. proj + bias + residual -> out (fp32)
    gemm_pl_k<1><<<dim3(D / 128, T / 64), 128>>>(fcb, D4, projw, D, out, D,
                                                 proj_b, res, T, D, D4, 0, 0);
}

// round 12
// speedup vs baseline: 1.1640x; 1.1640x over previous
#include <cuda_runtime.h>
#include <math.h>
#include <stdint.h>

#define T 2048
#define D 768
#define NH 12
#define DH 64
#define D3 2304
#define D4 3072

// packed projection layout
#define NB     3276
#define C_QKV  0
#define C_GEOV 2304
#define C_W1   3072
#define C_W2   3120
#define C_R1   3168
#define C_R2   3216
#define C_GATE 3264

// ---------------- scratch (static device globals; no allocation) ----------------
__device__ float g_ln1[T * D];
__device__ float g_big[T * NB];
__device__ float g_bigw[D * NB];
__device__ float g_bigb[NB];
__device__ float g_fcw[D * D4];
__device__ float g_projw[D4 * D];
__device__ float g_outw[D * D];
__device__ float g_jw[T * NH * 6];
__device__ float g_rd[T * NH * 6];
__device__ float g_gate[T];
__device__ float g_pstd[T * D];
__device__ float g_pgeo[T * D];
__device__ float g_comb[T * D];
__device__ float g_res[T * D];
__device__ float g_m[T * D];
__device__ float g_fc[T * D4];

__device__ __forceinline__ float gelu_f(float v) {
    const float c = 0.7978845608028654f;
    float u = c * (v + 0.044715f * v * v * v);
    return 0.5f * v * (1.0f + tanhf(u));
}

__device__ __forceinline__ uint32_t f2tf32(float x) {
    uint32_t r;
    asm("cvt.rna.tf32.f32 %0, %1;" : "=r"(r) : "f"(x));
    return r;
}
__device__ __forceinline__ float tf32bits(float x) {
    return __uint_as_float(f2tf32(x));
}

__device__ __forceinline__ void mma_tf32(float c[4], const uint32_t a[4], const uint32_t b[2]) {
    asm volatile(
        "mma.sync.aligned.m16n8k8.row.col.f32.tf32.tf32.f32 "
        "{%0,%1,%2,%3},{%4,%5,%6,%7},{%8,%9},{%0,%1,%2,%3};"
        : "+f"(c[0]), "+f"(c[1]), "+f"(c[2]), "+f"(c[3])
        : "r"(a[0]), "r"(a[1]), "r"(a[2]), "r"(a[3]), "r"(b[0]), "r"(b[1]));
}

__device__ __forceinline__ void cpa16(void* dst, const void* src, bool pred) {
    uint32_t d = (uint32_t)__cvta_generic_to_shared(dst);
    int sz = pred ? 16 : 0;
    asm volatile("cp.async.ca.shared.global [%0], [%1], 16, %2;"
                 :: "r"(d), "l"(src), "r"(sz));
}
#define CP_COMMIT() asm volatile("cp.async.commit_group;")
#define CP_WAIT1()  asm volatile("cp.async.wait_group 1;" ::: "memory")

// ---------------- pipelined tf32 GEMM (R10 shape; Bs padded to 136 for conflict-free reads) ----------------
template<int CFG>
__global__ void gemm_pl_k(const float* __restrict__ A, int lda,
                          const float* __restrict__ B, int ldb,
                          float* __restrict__ C, int ldc,
                          const float* __restrict__ bias,
                          const float* __restrict__ resid,
                          int M, int N, int K, int act, int roundOut)
{
    constexpr int BMt = CFG ? 64 : 128;
    constexpr int NI  = CFG ? 4 : 8;

    const int bm0 = blockIdx.y * BMt, bn0 = blockIdx.x * 128;

    __shared__ float As[2][BMt][20];
    __shared__ float Bs[2][16][136];   // stride 136 ≡ 8 mod 32: bank = 8*qid+grp, conflict-free

    const int tid = threadIdx.x, lane = tid & 31, wid = tid >> 5;
    const int wm = CFG ? (wid & 1) * 32 : (wid & 3) * 32;
    const int wn = CFG ? (wid >> 1) * 32 : (wid >> 2) * 64;
    const int grp = lane >> 2, qid = lane & 3;

    float acc[2][NI][4];
#pragma unroll
    for (int mi = 0; mi < 2; mi++)
#pragma unroll
        for (int ni = 0; ni < NI; ni++)
#pragma unroll
            for (int r = 0; r < 4; r++) acc[mi][ni][r] = 0.f;

    auto prefetch = [&](int pb, int k0) {
#pragma unroll
        for (int i = tid; i < BMt * 4; i += 256) {
            int row = i >> 2, kq = i & 3;
            cpa16(&As[pb][row][kq * 4],
                  &A[(size_t)(bm0 + row) * lda + k0 + kq * 4], true);
        }
#pragma unroll
        for (int i = tid; i < 512; i += 256) {
            int k = i >> 5, nq = i & 31;
            int gn = bn0 + nq * 4;
            cpa16(&Bs[pb][k][nq * 4],
                  &B[(size_t)(k0 + k) * ldb + gn], gn < N);
        }
    };

    prefetch(0, 0);
    CP_COMMIT();
    int buf = 0;
    for (int k0 = 0; k0 < K; k0 += 16) {
        if (k0 + 16 < K) prefetch(buf ^ 1, k0 + 16);
        CP_COMMIT();
        CP_WAIT1();
        __syncthreads();
#pragma unroll
        for (int ks = 0; ks < 16; ks += 8) {
            uint32_t af[2][4];
#pragma unroll
            for (int mi = 0; mi < 2; mi++) {
                int m0 = wm + mi * 16;
                af[mi][0] = __float_as_uint(As[buf][m0 + grp][ks + qid]);
                af[mi][1] = __float_as_uint(As[buf][m0 + grp + 8][ks + qid]);
                af[mi][2] = __float_as_uint(As[buf][m0 + grp][ks + qid + 4]);
                af[mi][3] = __float_as_uint(As[buf][m0 + grp + 8][ks + qid + 4]);
            }
#pragma unroll
            for (int ni = 0; ni < NI; ni++) {
                int n0 = wn + ni * 8;
                uint32_t bf[2];
                bf[0] = __float_as_uint(Bs[buf][ks + qid][n0 + grp]);
                bf[1] = __float_as_uint(Bs[buf][ks + qid + 4][n0 + grp]);
#pragma unroll
                for (int mi = 0; mi < 2; mi++)
                    mma_tf32(acc[mi][ni], af[mi], bf);
            }
        }
        __syncthreads();
        buf ^= 1;
    }

#pragma unroll
    for (int mi = 0; mi < 2; mi++) {
#pragma unroll
        for (int ni = 0; ni < NI; ni++) {
            int colb = bn0 + wn + ni * 8 + qid * 2;
#pragma unroll
            for (int r = 0; r < 2; r++) {
                int row = bm0 + wm + mi * 16 + grp + r * 8;
#pragma unroll
                for (int cs = 0; cs < 2; cs++) {
                    int c = colb + cs;
                    if (c >= N) continue;
                    float v = acc[mi][ni][r * 2 + cs];
                    if (bias) v += bias[c];
                    if (act) v = gelu_f(v);
                    if (resid) v += resid[(size_t)row * ldc + c];
                    if (roundOut) v = tf32bits(v);
                    C[(size_t)row * ldc + c] = v;
                }
            }
        }
    }
}

// ---------------- weight/bias pack (bigw stored tf32-rounded) ----------------
__global__ void pack_k(const float* __restrict__ qkv_w, const float* __restrict__ geov_w,
                       const float* __restrict__ w1w, const float* __restrict__ w2w,
                       const float* __restrict__ w1r, const float* __restrict__ w2r,
                       const float* __restrict__ gate_w,
                       const float* __restrict__ qkv_b, const float* __restrict__ geov_b,
                       const float* __restrict__ gate_b,
                       float* __restrict__ bigw, float* __restrict__ bigb)
{
    int col = blockIdx.x * 256 + threadIdx.x;
    int k = blockIdx.y;
    if (col >= NB) return;
    float v;
    if      (col < C_GEOV) v = qkv_w[(size_t)k * D3 + col];
    else if (col < C_W1)   v = geov_w[(size_t)k * D + (col - C_GEOV)];
    else if (col < C_W2)   v = w1w[(size_t)k * 48 + (col - C_W1)];
    else if (col < C_R1)   v = w2w[(size_t)k * 48 + (col - C_W2)];
    else if (col < C_R2)   v = w1r[(size_t)k * 48 + (col - C_R1)];
    else if (col < C_GATE) v = w2r[(size_t)k * 48 + (col - C_R2)];
    else                   v = gate_w[(size_t)k * NH + (col - C_GATE)];
    bigw[(size_t)k * NB + col] = tf32bits(v);
    if (k == 0) {
        float b;
        if      (col < C_GEOV) b = qkv_b[col];
        else if (col < C_W1)   b = geov_b[col - C_GEOV];
        else if (col < C_GATE) b = 0.f;
        else                   b = gate_b[col - C_GATE];
        bigb[col] = b;
    }
}

// ---------------- weight converts: fc/proj/out rounded copies ----------------
__global__ void convw_k(const float* __restrict__ fw, const float* __restrict__ pw,
                        const float* __restrict__ ow,
                        float* __restrict__ gfw, float* __restrict__ gpw,
                        float* __restrict__ gow)
{
    int i = blockIdx.x * 256 + threadIdx.x;
    if (i < D * D4) {
        gfw[i] = tf32bits(fw[i]);
        gpw[i] = tf32bits(pw[i]);
    }
    if (i < D * D) gow[i] = tf32bits(ow[i]);
}

// ---------------- flash attention body (R10; V pitch 72 for conflict-free PV reads) ----------------
template<int KD, int KLEN>
__device__ __forceinline__ void flash_body(
    const float* __restrict__ Qb, int qrs, int qhs,
    const float* __restrict__ Kb, int krs, int khs,
    const float* __restrict__ Vb, int vrs, int vhs,
    const float* __restrict__ scaleArr, float cscale,
    float* __restrict__ Ob,
    float* __restrict__ bufm, float* __restrict__ Vsm)
{
#define BUF(r, c) bufm[(r) * 68 + (c)]
#define VSM(r, c) Vsm[(r) * 72 + (c)]
    const int qb = gridDim.x - 1 - (int)blockIdx.x;   // LPT: heaviest first
    const int h = blockIdx.y;
    const int q0 = qb * 64;
    const int tid = threadIdx.x, lane = tid & 31, w = tid >> 5;
    const int grp = lane >> 2, qid = lane & 3;
    const int wm = w * 16;

    const float scale = scaleArr ? scaleArr[h] : cscale;

    if (KD == 64) {
        for (int i = tid; i < 64 * 16; i += 128) {
            int r = i >> 4, c4 = (i & 15) * 4;
            float4 v = *(const float4*)&Qb[(size_t)(q0 + r) * qrs + h * qhs + c4];
            BUF(r, c4)     = tf32bits(v.x);
            BUF(r, c4 + 1) = tf32bits(v.y);
            BUF(r, c4 + 2) = tf32bits(v.z);
            BUF(r, c4 + 3) = tf32bits(v.w);
        }
    } else {
        for (int i = tid; i < 64 * KD; i += 128) {
            int r = i / KD, c = i % KD;
            float v = (c < KLEN) ? Qb[(size_t)(q0 + r) * qrs + h * qhs + c] : 0.f;
            BUF(r, c) = tf32bits(v);
        }
    }
    __syncthreads();

    uint32_t qf[KD / 8][4];
#pragma unroll
    for (int s = 0; s < KD / 8; s++) {
        int ks = s * 8;
        qf[s][0] = __float_as_uint(BUF(wm + grp, ks + qid));
        qf[s][1] = __float_as_uint(BUF(wm + grp + 8, ks + qid));
        qf[s][2] = __float_as_uint(BUF(wm + grp, ks + qid + 4));
        qf[s][3] = __float_as_uint(BUF(wm + grp + 8, ks + qid + 4));
    }

    float m0 = -1e30f, m1 = -1e30f, l0 = 0.f, l1 = 0.f;
    float oacc[8][4] = {};
    const int rowg0 = q0 + wm + grp, rowg1 = rowg0 + 8;
    const int nkb = qb + 1;

    for (int kb = 0; kb < nkb; kb++) {
        const int s0 = kb * 64;
        __syncthreads();
        if (KD == 64) {
            for (int i = tid; i < 64 * 16; i += 128) {
                int r = i >> 4, c4 = (i & 15) * 4;
                float4 v = *(const float4*)&Kb[(size_t)(s0 + r) * krs + h * khs + c4];
                BUF(r, c4)     = tf32bits(v.x);
                BUF(r, c4 + 1) = tf32bits(v.y);
                BUF(r, c4 + 2) = tf32bits(v.z);
                BUF(r, c4 + 3) = tf32bits(v.w);
            }
        } else {
            for (int i = tid; i < 64 * KD; i += 128) {
                int r = i / KD, c = i % KD;
                float v = (c < KLEN) ? Kb[(size_t)(s0 + r) * krs + h * khs + c] : 0.f;
                BUF(r, c) = tf32bits(v);
            }
        }
        for (int i = tid; i < 64 * 16; i += 128) {
            int r = i >> 4, c4 = (i & 15) * 4;
            float4 v = *(const float4*)&Vb[(size_t)(s0 + r) * vrs + h * vhs + c4];
            VSM(r, c4)     = tf32bits(v.x);
            VSM(r, c4 + 1) = tf32bits(v.y);
            VSM(r, c4 + 2) = tf32bits(v.z);
            VSM(r, c4 + 3) = tf32bits(v.w);
        }
        __syncthreads();

        float sacc[8][4] = {};
#pragma unroll
        for (int s = 0; s < KD / 8; s++) {
            int ks = s * 8;
#pragma unroll
            for (int ni = 0; ni < 8; ni++) {
                uint32_t bf[2];
                bf[0] = __float_as_uint(BUF(ni * 8 + grp, ks + qid));
                bf[1] = __float_as_uint(BUF(ni * 8 + grp, ks + qid + 4));
                mma_tf32(sacc[ni], qf[s], bf);
            }
        }

        const bool dMask = (kb == nkb - 1);
#pragma unroll
        for (int ni = 0; ni < 8; ni++)
#pragma unroll
            for (int e = 0; e < 4; e++) {
                float v = sacc[ni][e] * scale;
                if (dMask) {
                    int col = s0 + ni * 8 + qid * 2 + (e & 1);
                    int row = (e < 2) ? rowg0 : rowg1;
                    if (col > row) v = -1e30f;
                }
                sacc[ni][e] = v;
            }

        float tm0 = -1e30f, tm1 = -1e30f;
#pragma unroll
        for (int ni = 0; ni < 8; ni++) {
            tm0 = fmaxf(tm0, fmaxf(sacc[ni][0], sacc[ni][1]));
            tm1 = fmaxf(tm1, fmaxf(sacc[ni][2], sacc[ni][3]));
        }
        tm0 = fmaxf(tm0, __shfl_xor_sync(0xffffffff, tm0, 1));
        tm0 = fmaxf(tm0, __shfl_xor_sync(0xffffffff, tm0, 2));
        tm1 = fmaxf(tm1, __shfl_xor_sync(0xffffffff, tm1, 1));
        tm1 = fmaxf(tm1, __shfl_xor_sync(0xffffffff, tm1, 2));

        const float mn0 = fmaxf(m0, tm0), mn1 = fmaxf(m1, tm1);
        const float a0 = __expf(m0 - mn0), a1 = __expf(m1 - mn1);
        m0 = mn0; m1 = mn1;

        float rs0 = 0.f, rs1 = 0.f;
#pragma unroll
        for (int ni = 0; ni < 8; ni++) {
            float p0 = __expf(sacc[ni][0] - mn0);
            float p1 = __expf(sacc[ni][1] - mn0);
            float p2 = __expf(sacc[ni][2] - mn1);
            float p3 = __expf(sacc[ni][3] - mn1);
            sacc[ni][0] = p0; sacc[ni][1] = p1; sacc[ni][2] = p2; sacc[ni][3] = p3;
            rs0 += p0 + p1; rs1 += p2 + p3;
        }
        rs0 += __shfl_xor_sync(0xffffffff, rs0, 1);
        rs0 += __shfl_xor_sync(0xffffffff, rs0, 2);
        rs1 += __shfl_xor_sync(0xffffffff, rs1, 1);
        rs1 += __shfl_xor_sync(0xffffffff, rs1, 2);
        l0 = l0 * a0 + rs0;
        l1 = l1 * a1 + rs1;

#pragma unroll
        for (int ni = 0; ni < 8; ni++) {
            oacc[ni][0] *= a0; oacc[ni][1] *= a0;
            oacc[ni][2] *= a1; oacc[ni][3] *= a1;
        }

        __syncthreads();
#pragma unroll
        for (int ni = 0; ni < 8; ni++) {
            int c = ni * 8 + qid * 2;
            BUF(wm + grp, c)         = tf32bits(sacc[ni][0]);
            BUF(wm + grp, c + 1)     = tf32bits(sacc[ni][1]);
            BUF(wm + grp + 8, c)     = tf32bits(sacc[ni][2]);
            BUF(wm + grp + 8, c + 1) = tf32bits(sacc[ni][3]);
        }
        __syncwarp();

#pragma unroll
        for (int ks = 0; ks < 64; ks += 8) {
            uint32_t af[4];
            af[0] = __float_as_uint(BUF(wm + grp, ks + qid));
            af[1] = __float_as_uint(BUF(wm + grp + 8, ks + qid));
            af[2] = __float_as_uint(BUF(wm + grp, ks + qid + 4));
            af[3] = __float_as_uint(BUF(wm + grp + 8, ks + qid + 4));
#pragma unroll
            for (int ni = 0; ni < 8; ni++) {
                uint32_t bf[2];
                bf[0] = __float_as_uint(VSM(ks + qid, ni * 8 + grp));
                bf[1] = __float_as_uint(VSM(ks + qid + 4, ni * 8 + grp));
                mma_tf32(oacc[ni], af, bf);
            }
        }
        __syncwarp();
    }

    const float inv0 = 1.f / l0, inv1 = 1.f / l1;
#pragma unroll
    for (int ni = 0; ni < 8; ni++) {
        int c = ni * 8 + qid * 2;
        Ob[(size_t)rowg0 * D + h * DH + c]     = oacc[ni][0] * inv0;
        Ob[(size_t)rowg0 * D + h * DH + c + 1] = oacc[ni][1] * inv0;
        Ob[(size_t)rowg1 * D + h * DH + c]     = oacc[ni][2] * inv1;
        Ob[(size_t)rowg1 * D + h * DH + c + 1] = oacc[ni][3] * inv1;
    }
#undef BUF
#undef VSM
}

// ---------------- merged std+geo flash ----------------
__global__ void flash_dual_k(const float* __restrict__ big,
                             const float* __restrict__ rd,
                             const float* __restrict__ jw,
                             const float* __restrict__ inc,
                             float* __restrict__ pstd,
                             float* __restrict__ pgeo)
{
    __shared__ float buf[64 * 68];
    __shared__ float Vs[64 * 72];
    if (blockIdx.z == 0) {
        flash_body<64, 64>(big + C_QKV, NB, DH,
                           big + C_QKV + D, NB, DH,
                           big + C_QKV + 2 * D, NB, DH,
                           nullptr, 0.125f, pstd, buf, Vs);
    } else {
        flash_body<8, 6>(rd, NH * 6, 6, jw, NH * 6, 6,
                         big + C_GEOV, NB, DH,
                         inc, 0.f, pgeo, buf, Vs);
    }
}

// ---------------- layernorm (optional tf32-rounded output) ----------------
__global__ void layernorm_k(const float* __restrict__ x, const float* __restrict__ g,
                            const float* __restrict__ b, float* __restrict__ y,
                            int roundOut)
{
    int t = blockIdx.x;
    const float* row = x + (size_t)t * D;
    __shared__ float sh[256];
    int tid = threadIdx.x;
    float s = 0.f;
    for (int i = tid; i < D; i += 256) s += row[i];
    sh[tid] = s; __syncthreads();
    for (int st = 128; st > 0; st >>= 1) { if (tid < st) sh[tid] += sh[tid + st]; __syncthreads(); }
    float mean = sh[0] / D;
    __syncthreads();
    float v = 0.f;
    for (int i = tid; i < D; i += 256) { float d = row[i] - mean; v += d * d; }
    sh[tid] = v; __syncthreads();
    for (int st = 128; st > 0; st >>= 1) { if (tid < st) sh[tid] += sh[tid + st]; __syncthreads(); }
    float rstd = rsqrtf(sh[0] / D + 1e-5f);
    for (int i = tid; i < D; i += 256) {
        float o = (row[i] - mean) * rstd * g[i] + b[i];
        y[(size_t)t * D + i] = roundOut ? tf32bits(o) : o;
    }
}

// ---------------- Plucker exterior + J6 + gate (merged) ----------------
__device__ __forceinline__ void exterior6(const float* a, const float* b, float* L)
{
    L[0] = a[0] * b[1] - a[1] * b[0];
    L[1] = a[0] * b[2] - a[2] * b[0];
    L[2] = a[0] * b[3] - a[3] * b[0];
    L[3] = a[1] * b[2] - a[2] * b[1];
    L[4] = a[1] * b[3] - a[3] * b[1];
    L[5] = a[2] * b[3] - a[3] * b[2];
    float n = sqrtf(L[0]*L[0] + L[1]*L[1] + L[2]*L[2] + L[3]*L[3] + L[4]*L[4] + L[5]*L[5]);
    float inv = 1.0f / fmaxf(n, 1e-12f);
#pragma unroll
    for (int i = 0; i < 6; i++) L[i] *= inv;
}

__global__ void linesgate_k(const float* __restrict__ big,
                            float* __restrict__ jw, float* __restrict__ rd,
                            float* __restrict__ gate)
{
    int idx = blockIdx.x * blockDim.x + threadIdx.x;
    if (idx < T) {
        const float* row = big + (size_t)idx * NB + C_GATE;
        float s = 0.f;
#pragma unroll
        for (int h = 0; h < NH; h++) s += 1.f / (1.f + __expf(-row[h]));
        gate[idx] = s / NH;
    }
    if (idx >= T * NH) return;
    int t = idx / NH, h = idx % NH;
    float a[4], b[4], L[6];
#pragma unroll
    for (int j = 0; j < 4; j++)
        a[j] = (t > 0) ? big[(size_t)(t - 1) * NB + C_W1 + h * 4 + j] : 0.f;
#pragma unroll
    for (int j = 0; j < 4; j++) b[j] = big[(size_t)t * NB + C_W2 + h * 4 + j];
    exterior6(a, b, L);
    float* o = jw + (size_t)idx * 6;
    o[0] =  L[5]; o[1] = -L[4]; o[2] =  L[3];
    o[3] =  L[2]; o[4] = -L[1]; o[5] =  L[0];
#pragma unroll
    for (int j = 0; j < 4; j++) a[j] = big[(size_t)t * NB + C_R1 + h * 4 + j];
#pragma unroll
    for (int j = 0; j < 4; j++) b[j] = big[(size_t)t * NB + C_R2 + h * 4 + j];
    exterior6(a, b, L);
    float* p = rd + (size_t)idx * 6;
#pragma unroll
    for (int i = 0; i < 6; i++) p[i] = L[i];
}

// ---------------- combine gate (tf32-rounded output; feeds out-proj A) ----------------
__global__ void combine_k(const float* __restrict__ so, const float* __restrict__ go,
                          const float* __restrict__ gate, float* __restrict__ out)
{
    int idx = blockIdx.x * 256 + threadIdx.x;
    if (idx >= T * D) return;
    float g = gate[idx / D];
    out[idx] = tf32bits((1.f - g) * so[idx] + g * go[idx]);
}

// ---------------- host launch ----------------
static float* symAddr(const void* sym)
{
    void* p = nullptr;
    cudaGetSymbolAddress(&p, sym);
    return (float*)p;
}

extern "C" void kernel_launch(void* const* d_in, const int* in_sizes, int n_in,
                              void* d_out, int out_size)
{
    const float* x       = (const float*)d_in[0];
    const float* ln1_g   = (const float*)d_in[1];
    const float* ln1_b   = (const float*)d_in[2];
    const float* qkv_w   = (const float*)d_in[3];
    const float* qkv_b   = (const float*)d_in[4];
    const float* w1w     = (const float*)d_in[5];
    const float* w2w     = (const float*)d_in[6];
    const float* w1r     = (const float*)d_in[7];
    const float* w2r     = (const float*)d_in[8];
    const float* geov_w  = (const float*)d_in[9];
    const float* geov_b  = (const float*)d_in[10];
    const float* gate_w  = (const float*)d_in[11];
    const float* gate_b  = (const float*)d_in[12];
    const float* inc     = (const float*)d_in[13];
    const float* out_w   = (const float*)d_in[14];
    const float* out_b   = (const float*)d_in[15];
    const float* ln2_g   = (const float*)d_in[16];
    const float* ln2_b   = (const float*)d_in[17];
    const float* fc_w    = (const float*)d_in[18];
    const float* fc_b    = (const float*)d_in[19];
    const float* proj_w  = (const float*)d_in[20];
    const float* proj_b  = (const float*)d_in[21];
    float* out = (float*)d_out;

    float* ln1   = symAddr(g_ln1);
    float* big   = symAddr(g_big);
    float* bigw  = symAddr(g_bigw);
    float* bigb  = symAddr(g_bigb);
    float* fcw   = symAddr(g_fcw);
    float* projw = symAddr(g_projw);
    float* outw  = symAddr(g_outw);
    float* jw    = symAddr(g_jw);
    float* rd    = symAddr(g_rd);
    float* gate  = symAddr(g_gate);
    float* pstd  = symAddr(g_pstd);
    float* pgeo  = symAddr(g_pgeo);
    float* comb  = symAddr(g_comb);
    float* res   = symAddr(g_res);
    float* mbuf  = symAddr(g_m);
    float* fcb   = symAddr(g_fc);

    // 1. pack weights (tf32) + biases; convert fc/proj/out weights
    pack_k<<<dim3((NB + 255) / 256, D), 256>>>(qkv_w, geov_w, w1w, w2w, w1r, w2r, gate_w,
                                               qkv_b, geov_b, gate_b, bigw, bigb);
    convw_k<<<(D * D4 + 255) / 256, 256>>>(fc_w, proj_w, out_w, fcw, projw, outw);

    // 2. ln1 (tf32-rounded; feeds mega-GEMM A)
    layernorm_k<<<T, 256>>>(x, ln1_g, ln1_b, ln1, 1);

    // 3. mega-GEMM: big = ln1 @ bigw + bigb
    gemm_pl_k<0><<<dim3((NB + 127) / 128, T / 128), 256>>>(ln1, D, bigw, NB, big, NB,
                                                           bigb, nullptr, T, NB, D, 0, 0);

    // 4. exterior + J6 + gate
    linesgate_k<<<(T * NH + 255) / 256, 256>>>(big, jw, rd, gate);

    // 5. merged std + geo flash attention
    flash_dual_k<<<dim3(T / 64, NH, 2), 128>>>(big, rd, jw, inc, pstd, pgeo);

    // 6. combine (rounded; feeds out-proj A)
    combine_k<<<(T * D + 255) / 256, 256>>>(pstd, pgeo, gate, comb);

    // 7. out proj + residual (res stays fp32)
    gemm_pl_k<1><<<dim3(D / 128, T / 64), 256>>>(comb, D, outw, D, res, D,
                                                 out_b, x, T, D, D, 0, 0);

    // 8. ln2 (rounded; feeds fc A)
    layernorm_k<<<T, 256>>>(res, ln2_g, ln2_b, mbuf, 1);

    // 9. fc + gelu (rounded output; feeds proj A)
    gemm_pl_k<0><<<dim3(D4 / 128, T / 128), 256>>>(mbuf, D, fcw, D4, fcb, D4,
                                                   fc_b, nullptr, T, D4, D, 1, 1);

    // 10. proj + bias + residual -> out (fp32)
    gemm_pl_k<1><<<dim3(D / 128, T / 64), 256>>>(fcb, D4, projw, D, out, D,
                                                 proj_b, res, T, D, D4, 0, 0);
}

// round 14
// speedup vs baseline: 1.1961x; 1.0276x over previous
#include <cuda_runtime.h>
#include <math.h>
#include <stdint.h>

#define T 2048
#define D 768
#define NH 12
#define DH 64
#define D3 2304
#define D4 3072

// packed projection layout
#define NB     3276
#define C_QKV  0
#define C_GEOV 2304
#define C_W1   3072
#define C_W2   3120
#define C_R1   3168
#define C_R2   3216
#define C_GATE 3264

// ---------------- scratch (static device globals; no allocation) ----------------
__device__ float g_ln1[T * D];
__device__ float g_big[T * NB];
__device__ float g_bigw[D * NB];
__device__ float g_bigb[NB];
__device__ float g_fcw[D * D4];
__device__ float g_projw[D4 * D];
__device__ float g_outw[D * D];
__device__ float g_jw[T * NH * 6];
__device__ float g_rd[T * NH * 6];
__device__ float g_gate[T];
__device__ float g_pstd[T * D];
__device__ float g_pgeo[T * D];
__device__ float g_comb[T * D];
__device__ float g_res[T * D];
__device__ float g_m[T * D];
__device__ float g_fc[T * D4];

__device__ __forceinline__ float gelu_f(float v) {
    const float c = 0.7978845608028654f;
    float u = c * (v + 0.044715f * v * v * v);
    return 0.5f * v * (1.0f + tanhf(u));
}

__device__ __forceinline__ uint32_t f2tf32(float x) {
    uint32_t r;
    asm("cvt.rna.tf32.f32 %0, %1;" : "=r"(r) : "f"(x));
    return r;
}
__device__ __forceinline__ float tf32bits(float x) {
    return __uint_as_float(f2tf32(x));
}

__device__ __forceinline__ void mma_tf32(float c[4], const uint32_t a[4], const uint32_t b[2]) {
    asm volatile(
        "mma.sync.aligned.m16n8k8.row.col.f32.tf32.tf32.f32 "
        "{%0,%1,%2,%3},{%4,%5,%6,%7},{%8,%9},{%0,%1,%2,%3};"
        : "+f"(c[0]), "+f"(c[1]), "+f"(c[2]), "+f"(c[3])
        : "r"(a[0]), "r"(a[1]), "r"(a[2]), "r"(a[3]), "r"(b[0]), "r"(b[1]));
}

__device__ __forceinline__ void cpa16(void* dst, const void* src, bool pred) {
    uint32_t d = (uint32_t)__cvta_generic_to_shared(dst);
    int sz = pred ? 16 : 0;
    asm volatile("cp.async.ca.shared.global [%0], [%1], 16, %2;"
                 :: "r"(d), "l"(src), "r"(sz));
}
#define CP_COMMIT() asm volatile("cp.async.commit_group;")
#define CP_WAIT1()  asm volatile("cp.async.wait_group 1;" ::: "memory")

// ---------------- pipelined tf32 GEMM; main loop unrolled x2 (static buffer idx) ----------------
template<int CFG>
__global__ void gemm_pl_k(const float* __restrict__ A, int lda,
                          const float* __restrict__ B, int ldb,
                          float* __restrict__ C, int ldc,
                          const float* __restrict__ bias,
                          const float* __restrict__ resid,
                          int M, int N, int K, int act, int roundOut)
{
    constexpr int BMt = CFG ? 64 : 128;
    constexpr int NI  = CFG ? 4 : 8;

    const int bm0 = blockIdx.y * BMt, bn0 = blockIdx.x * 128;

    __shared__ float As[2][BMt][20];
    __shared__ float Bs[2][16][136];   // stride 136 ≡ 8 mod 32: conflict-free fragment reads

    const int tid = threadIdx.x, lane = tid & 31, wid = tid >> 5;
    const int wm = CFG ? (wid & 1) * 32 : (wid & 3) * 32;
    const int wn = CFG ? (wid >> 1) * 32 : (wid >> 2) * 64;
    const int grp = lane >> 2, qid = lane & 3;

    float acc[2][NI][4];
#pragma unroll
    for (int mi = 0; mi < 2; mi++)
#pragma unroll
        for (int ni = 0; ni < NI; ni++)
#pragma unroll
            for (int r = 0; r < 4; r++) acc[mi][ni][r] = 0.f;

    auto prefetch = [&](int pb, int k0) {
#pragma unroll
        for (int i = tid; i < BMt * 4; i += 256) {
            int row = i >> 2, kq = i & 3;
            cpa16(&As[pb][row][kq * 4],
                  &A[(size_t)(bm0 + row) * lda + k0 + kq * 4], true);
        }
#pragma unroll
        for (int i = tid; i < 512; i += 256) {
            int k = i >> 5, nq = i & 31;
            int gn = bn0 + nq * 4;
            cpa16(&Bs[pb][k][nq * 4],
                  &B[(size_t)(k0 + k) * ldb + gn], gn < N);
        }
    };

    auto computeTile = [&](int cb) {
#pragma unroll
        for (int ks = 0; ks < 16; ks += 8) {
            uint32_t af[2][4];
#pragma unroll
            for (int mi = 0; mi < 2; mi++) {
                int m0 = wm + mi * 16;
                af[mi][0] = __float_as_uint(As[cb][m0 + grp][ks + qid]);
                af[mi][1] = __float_as_uint(As[cb][m0 + grp + 8][ks + qid]);
                af[mi][2] = __float_as_uint(As[cb][m0 + grp][ks + qid + 4]);
                af[mi][3] = __float_as_uint(As[cb][m0 + grp + 8][ks + qid + 4]);
            }
#pragma unroll
            for (int ni = 0; ni < NI; ni++) {
                int n0 = wn + ni * 8;
                uint32_t bf[2];
                bf[0] = __float_as_uint(Bs[cb][ks + qid][n0 + grp]);
                bf[1] = __float_as_uint(Bs[cb][ks + qid + 4][n0 + grp]);
#pragma unroll
                for (int mi = 0; mi < 2; mi++)
                    mma_tf32(acc[mi][ni], af[mi], bf);
            }
        }
    };

    prefetch(0, 0);
    CP_COMMIT();
    // K is a multiple of 32 for all launches -> unroll by 2 with static buffer index
    for (int k0 = 0; k0 < K; k0 += 32) {
        if (k0 + 16 < K) prefetch(1, k0 + 16);
        CP_COMMIT();
        CP_WAIT1();
        __syncthreads();
        computeTile(0);
        __syncthreads();

        if (k0 + 32 < K) prefetch(0, k0 + 32);
        CP_COMMIT();
        CP_WAIT1();
        __syncthreads();
        computeTile(1);
        __syncthreads();
    }

#pragma unroll
    for (int mi = 0; mi < 2; mi++) {
#pragma unroll
        for (int ni = 0; ni < NI; ni++) {
            int colb = bn0 + wn + ni * 8 + qid * 2;
#pragma unroll
            for (int r = 0; r < 2; r++) {
                int row = bm0 + wm + mi * 16 + grp + r * 8;
#pragma unroll
                for (int cs = 0; cs < 2; cs++) {
                    int c = colb + cs;
                    if (c >= N) continue;
                    float v = acc[mi][ni][r * 2 + cs];
                    if (bias) v += bias[c];
                    if (act) v = gelu_f(v);
                    if (resid) v += resid[(size_t)row * ldc + c];
                    if (roundOut) v = tf32bits(v);
                    C[(size_t)row * ldc + c] = v;
                }
            }
        }
    }
}

// ---------------- weight/bias pack (bigw stored tf32-rounded) ----------------
__global__ void pack_k(const float* __restrict__ qkv_w, const float* __restrict__ geov_w,
                       const float* __restrict__ w1w, const float* __restrict__ w2w,
                       const float* __restrict__ w1r, const float* __restrict__ w2r,
                       const float* __restrict__ gate_w,
                       const float* __restrict__ qkv_b, const float* __restrict__ geov_b,
                       const float* __restrict__ gate_b,
                       float* __restrict__ bigw, float* __restrict__ bigb)
{
    int col = blockIdx.x * 256 + threadIdx.x;
    int k = blockIdx.y;
    if (col >= NB) return;
    float v;
    if      (col < C_GEOV) v = qkv_w[(size_t)k * D3 + col];
    else if (col < C_W1)   v = geov_w[(size_t)k * D + (col - C_GEOV)];
    else if (col < C_W2)   v = w1w[(size_t)k * 48 + (col - C_W1)];
    else if (col < C_R1)   v = w2w[(size_t)k * 48 + (col - C_W2)];
    else if (col < C_R2)   v = w1r[(size_t)k * 48 + (col - C_R1)];
    else if (col < C_GATE) v = w2r[(size_t)k * 48 + (col - C_R2)];
    else                   v = gate_w[(size_t)k * NH + (col - C_GATE)];
    bigw[(size_t)k * NB + col] = tf32bits(v);
    if (k == 0) {
        float b;
        if      (col < C_GEOV) b = qkv_b[col];
        else if (col < C_W1)   b = geov_b[col - C_GEOV];
        else if (col < C_GATE) b = 0.f;
        else                   b = gate_b[col - C_GATE];
        bigb[col] = b;
    }
}

// ---------------- weight converts: fc/proj/out rounded copies ----------------
__global__ void convw_k(const float* __restrict__ fw, const float* __restrict__ pw,
                        const float* __restrict__ ow,
                        float* __restrict__ gfw, float* __restrict__ gpw,
                        float* __restrict__ gow)
{
    int i = blockIdx.x * 256 + threadIdx.x;
    if (i < D * D4) {
        gfw[i] = tf32bits(fw[i]);
        gpw[i] = tf32bits(pw[i]);
    }
    if (i < D * D) gow[i] = tf32bits(ow[i]);
}

// ---------------- flash attention body (vectorized staging; V pitch 72) ----------------
template<int KD, int KLEN>
__device__ __forceinline__ void flash_body(
    const float* __restrict__ Qb, int qrs, int qhs,
    const float* __restrict__ Kb, int krs, int khs,
    const float* __restrict__ Vb, int vrs, int vhs,
    const float* __restrict__ scaleArr, float cscale,
    float* __restrict__ Ob,
    float* __restrict__ bufm, float* __restrict__ Vsm)
{
#define BUF(r, c) bufm[(r) * 68 + (c)]
#define VSM(r, c) Vsm[(r) * 72 + (c)]
    const int qb = gridDim.x - 1 - (int)blockIdx.x;   // LPT: heaviest first
    const int h = blockIdx.y;
    const int q0 = qb * 64;
    const int tid = threadIdx.x, lane = tid & 31, w = tid >> 5;
    const int grp = lane >> 2, qid = lane & 3;
    const int wm = w * 16;

    const float scale = scaleArr ? scaleArr[h] : cscale;

    if (KD == 64) {
        for (int i = tid; i < 64 * 16; i += 128) {
            int r = i >> 4, c4 = (i & 15) * 4;
            float4 v = *(const float4*)&Qb[(size_t)(q0 + r) * qrs + h * qhs + c4];
            float4 t;
            t.x = tf32bits(v.x); t.y = tf32bits(v.y);
            t.z = tf32bits(v.z); t.w = tf32bits(v.w);
            *(float4*)&BUF(r, c4) = t;
        }
    } else {
        for (int i = tid; i < 64 * KD; i += 128) {
            int r = i / KD, c = i % KD;
            float v = (c < KLEN) ? Qb[(size_t)(q0 + r) * qrs + h * qhs + c] : 0.f;
            BUF(r, c) = tf32bits(v);
        }
    }
    __syncthreads();

    uint32_t qf[KD / 8][4];
#pragma unroll
    for (int s = 0; s < KD / 8; s++) {
        int ks = s * 8;
        qf[s][0] = __float_as_uint(BUF(wm + grp, ks + qid));
        qf[s][1] = __float_as_uint(BUF(wm + grp + 8, ks + qid));
        qf[s][2] = __float_as_uint(BUF(wm + grp, ks + qid + 4));
        qf[s][3] = __float_as_uint(BUF(wm + grp + 8, ks + qid + 4));
    }

    float m0 = -1e30f, m1 = -1e30f, l0 = 0.f, l1 = 0.f;
    float oacc[8][4] = {};
    const int rowg0 = q0 + wm + grp, rowg1 = rowg0 + 8;
    const int nkb = qb + 1;

    for (int kb = 0; kb < nkb; kb++) {
        const int s0 = kb * 64;
        __syncthreads();
        if (KD == 64) {
            for (int i = tid; i < 64 * 16; i += 128) {
                int r = i >> 4, c4 = (i & 15) * 4;
                float4 v = *(const float4*)&Kb[(size_t)(s0 + r) * krs + h * khs + c4];
                float4 t;
                t.x = tf32bits(v.x); t.y = tf32bits(v.y);
                t.z = tf32bits(v.z); t.w = tf32bits(v.w);
                *(float4*)&BUF(r, c4) = t;
            }
        } else {
            for (int i = tid; i < 64 * KD; i += 128) {
                int r = i / KD, c = i % KD;
                float v = (c < KLEN) ? Kb[(size_t)(s0 + r) * krs + h * khs + c] : 0.f;
                BUF(r, c) = tf32bits(v);
            }
        }
        for (int i = tid; i < 64 * 16; i += 128) {
            int r = i >> 4, c4 = (i & 15) * 4;
            float4 v = *(const float4*)&Vb[(size_t)(s0 + r) * vrs + h * vhs + c4];
            float4 t;
            t.x = tf32bits(v.x); t.y = tf32bits(v.y);
            t.z = tf32bits(v.z); t.w = tf32bits(v.w);
            *(float4*)&VSM(r, c4) = t;
        }
        __syncthreads();

        float sacc[8][4] = {};
#pragma unroll
        for (int s = 0; s < KD / 8; s++) {
            int ks = s * 8;
#pragma unroll
            for (int ni = 0; ni < 8; ni++) {
                uint32_t bf[2];
                bf[0] = __float_as_uint(BUF(ni * 8 + grp, ks + qid));
                bf[1] = __float_as_uint(BUF(ni * 8 + grp, ks + qid + 4));
                mma_tf32(sacc[ni], qf[s], bf);
            }
        }

        const bool dMask = (kb == nkb - 1);
#pragma unroll
        for (int ni = 0; ni < 8; ni++)
#pragma unroll
            for (int e = 0; e < 4; e++) {
                float v = sacc[ni][e] * scale;
                if (dMask) {
                    int col = s0 + ni * 8 + qid * 2 + (e & 1);
                    int row = (e < 2) ? rowg0 : rowg1;
                    if (col > row) v = -1e30f;
                }
                sacc[ni][e] = v;
            }

        float tm0 = -1e30f, tm1 = -1e30f;
#pragma unroll
        for (int ni = 0; ni < 8; ni++) {
            tm0 = fmaxf(tm0, fmaxf(sacc[ni][0], sacc[ni][1]));
            tm1 = fmaxf(tm1, fmaxf(sacc[ni][2], sacc[ni][3]));
        }
        tm0 = fmaxf(tm0, __shfl_xor_sync(0xffffffff, tm0, 1));
        tm0 = fmaxf(tm0, __shfl_xor_sync(0xffffffff, tm0, 2));
        tm1 = fmaxf(tm1, __shfl_xor_sync(0xffffffff, tm1, 1));
        tm1 = fmaxf(tm1, __shfl_xor_sync(0xffffffff, tm1, 2));

        const float mn0 = fmaxf(m0, tm0), mn1 = fmaxf(m1, tm1);
        const float a0 = __expf(m0 - mn0), a1 = __expf(m1 - mn1);
        m0 = mn0; m1 = mn1;

        float rs0 = 0.f, rs1 = 0.f;
#pragma unroll
        for (int ni = 0; ni < 8; ni++) {
            float p0 = __expf(sacc[ni][0] - mn0);
            float p1 = __expf(sacc[ni][1] - mn0);
            float p2 = __expf(sacc[ni][2] - mn1);
            float p3 = __expf(sacc[ni][3] - mn1);
            sacc[ni][0] = p0; sacc[ni][1] = p1; sacc[ni][2] = p2; sacc[ni][3] = p3;
            rs0 += p0 + p1; rs1 += p2 + p3;
        }
        rs0 += __shfl_xor_sync(0xffffffff, rs0, 1);
        rs0 += __shfl_xor_sync(0xffffffff, rs0, 2);
        rs1 += __shfl_xor_sync(0xffffffff, rs1, 1);
        rs1 += __shfl_xor_sync(0xffffffff, rs1, 2);
        l0 = l0 * a0 + rs0;
        l1 = l1 * a1 + rs1;

#pragma unroll
        for (int ni = 0; ni < 8; ni++) {
            oacc[ni][0] *= a0; oacc[ni][1] *= a0;
            oacc[ni][2] *= a1; oacc[ni][3] *= a1;
        }

        __syncthreads();
        // stage P: STS.64 pairs (addresses 8B-aligned: pitch 68 even, c even)
#pragma unroll
        for (int ni = 0; ni < 8; ni++) {
            int c = ni * 8 + qid * 2;
            float2 p01 = make_float2(tf32bits(sacc[ni][0]), tf32bits(sacc[ni][1]));
            float2 p23 = make_float2(tf32bits(sacc[ni][2]), tf32bits(sacc[ni][3]));
            *(float2*)&BUF(wm + grp, c)     = p01;
            *(float2*)&BUF(wm + grp + 8, c) = p23;
        }
        __syncwarp();

#pragma unroll
        for (int ks = 0; ks < 64; ks += 8) {
            uint32_t af[4];
            af[0] = __float_as_uint(BUF(wm + grp, ks + qid));
            af[1] = __float_as_uint(BUF(wm + grp + 8, ks + qid));
            af[2] = __float_as_uint(BUF(wm + grp, ks + qid + 4));
            af[3] = __float_as_uint(BUF(wm + grp + 8, ks + qid + 4));
#pragma unroll
            for (int ni = 0; ni < 8; ni++) {
                uint32_t bf[2];
                bf[0] = __float_as_uint(VSM(ks + qid, ni * 8 + grp));
                bf[1] = __float_as_uint(VSM(ks + qid + 4, ni * 8 + grp));
                mma_tf32(oacc[ni], af, bf);
            }
        }
        __syncwarp();
    }

    const float inv0 = 1.f / l0, inv1 = 1.f / l1;
#pragma unroll
    for (int ni = 0; ni < 8; ni++) {
        int c = ni * 8 + qid * 2;
        Ob[(size_t)rowg0 * D + h * DH + c]     = oacc[ni][0] * inv0;
        Ob[(size_t)rowg0 * D + h * DH + c + 1] = oacc[ni][1] * inv0;
        Ob[(size_t)rowg1 * D + h * DH + c]     = oacc[ni][2] * inv1;
        Ob[(size_t)rowg1 * D + h * DH + c + 1] = oacc[ni][3] * inv1;
    }
#undef BUF
#undef VSM
}

// ---------------- merged std+geo flash ----------------
__global__ void flash_dual_k(const float* __restrict__ big,
                             const float* __restrict__ rd,
                             const float* __restrict__ jw,
                             const float* __restrict__ inc,
                             float* __restrict__ pstd,
                             float* __restrict__ pgeo)
{
    __shared__ float buf[64 * 68];
    __shared__ float Vs[64 * 72];
    if (blockIdx.z == 0) {
        flash_body<64, 64>(big + C_QKV, NB, DH,
                           big + C_QKV + D, NB, DH,
                           big + C_QKV + 2 * D, NB, DH,
                           nullptr, 0.125f, pstd, buf, Vs);
    } else {
        flash_body<8, 6>(rd, NH * 6, 6, jw, NH * 6, 6,
                         big + C_GEOV, NB, DH,
                         inc, 0.f, pgeo, buf, Vs);
    }
}

// ---------------- layernorm (optional tf32-rounded output) ----------------
__global__ void layernorm_k(const float* __restrict__ x, const float* __restrict__ g,
                            const float* __restrict__ b, float* __restrict__ y,
                            int roundOut)
{
    int t = blockIdx.x;
    const float* row = x + (size_t)t * D;
    __shared__ float sh[256];
    int tid = threadIdx.x;
    float s = 0.f;
    for (int i = tid; i < D; i += 256) s += row[i];
    sh[tid] = s; __syncthreads();
    for (int st = 128; st > 0; st >>= 1) { if (tid < st) sh[tid] += sh[tid + st]; __syncthreads(); }
    float mean = sh[0] / D;
    __syncthreads();
    float v = 0.f;
    for (int i = tid; i < D; i += 256) { float d = row[i] - mean; v += d * d; }
    sh[tid] = v; __syncthreads();
    for (int st = 128; st > 0; st >>= 1) { if (tid < st) sh[tid] += sh[tid + st]; __syncthreads(); }
    float rstd = rsqrtf(sh[0] / D + 1e-5f);
    for (int i = tid; i < D; i += 256) {
        float o = (row[i] - mean) * rstd * g[i] + b[i];
        y[(size_t)t * D + i] = roundOut ? tf32bits(o) : o;
    }
}

// ---------------- Plucker exterior + J6 + gate (merged) ----------------
__device__ __forceinline__ void exterior6(const float* a, const float* b, float* L)
{
    L[0] = a[0] * b[1] - a[1] * b[0];
    L[1] = a[0] * b[2] - a[2] * b[0];
    L[2] = a[0] * b[3] - a[3] * b[0];
    L[3] = a[1] * b[2] - a[2] * b[1];
    L[4] = a[1] * b[3] - a[3] * b[1];
    L[5] = a[2] * b[3] - a[3] * b[2];
    float n = sqrtf(L[0]*L[0] + L[1]*L[1] + L[2]*L[2] + L[3]*L[3] + L[4]*L[4] + L[5]*L[5]);
    float inv = 1.0f / fmaxf(n, 1e-12f);
#pragma unroll
    for (int i = 0; i < 6; i++) L[i] *= inv;
}

__global__ void linesgate_k(const float* __restrict__ big,
                            float* __restrict__ jw, float* __restrict__ rd,
                            float* __restrict__ gate)
{
    int idx = blockIdx.x * blockDim.x + threadIdx.x;
    if (idx < T) {
        const float* row = big + (size_t)idx * NB + C_GATE;
        float s = 0.f;
#pragma unroll
        for (int h = 0; h < NH; h++) s += 1.f / (1.f + __expf(-row[h]));
        gate[idx] = s / NH;
    }
    if (idx >= T * NH) return;
    int t = idx / NH, h = idx % NH;
    float a[4], b[4], L[6];
#pragma unroll
    for (int j = 0; j < 4; j++)
        a[j] = (t > 0) ? big[(size_t)(t - 1) * NB + C_W1 + h * 4 + j] : 0.f;
#pragma unroll
    for (int j = 0; j < 4; j++) b[j] = big[(size_t)t * NB + C_W2 + h * 4 + j];
    exterior6(a, b, L);
    float* o = jw + (size_t)idx * 6;
    o[0] =  L[5]; o[1] = -L[4]; o[2] =  L[3];
    o[3] =  L[2]; o[4] = -L[1]; o[5] =  L[0];
#pragma unroll
    for (int j = 0; j < 4; j++) a[j] = big[(size_t)t * NB + C_R1 + h * 4 + j];
#pragma unroll
    for (int j = 0; j < 4; j++) b[j] = big[(size_t)t * NB + C_R2 + h * 4 + j];
    exterior6(a, b, L);
    float* p = rd + (size_t)idx * 6;
#pragma unroll
    for (int i = 0; i < 6; i++) p[i] = L[i];
}

// ---------------- combine gate (tf32-rounded output; feeds out-proj A) ----------------
__global__ void combine_k(const float* __restrict__ so, const float* __restrict__ go,
                          const float* __restrict__ gate, float* __restrict__ out)
{
    int idx = blockIdx.x * 256 + threadIdx.x;
    if (idx >= T * D) return;
    float g = gate[idx / D];
    out[idx] = tf32bits((1.f - g) * so[idx] + g * go[idx]);
}

// ---------------- host launch ----------------
static float* symAddr(const void* sym)
{
    void* p = nullptr;
    cudaGetSymbolAddress(&p, sym);
    return (float*)p;
}

extern "C" void kernel_launch(void* const* d_in, const int* in_sizes, int n_in,
                              void* d_out, int out_size)
{
    const float* x       = (const float*)d_in[0];
    const float* ln1_g   = (const float*)d_in[1];
    const float* ln1_b   = (const float*)d_in[2];
    const float* qkv_w   = (const float*)d_in[3];
    const float* qkv_b   = (const float*)d_in[4];
    const float* w1w     = (const float*)d_in[5];
    const float* w2w     = (const float*)d_in[6];
    const float* w1r     = (const float*)d_in[7];
    const float* w2r     = (const float*)d_in[8];
    const float* geov_w  = (const float*)d_in[9];
    const float* geov_b  = (const float*)d_in[10];
    const float* gate_w  = (const float*)d_in[11];
    const float* gate_b  = (const float*)d_in[12];
    const float* inc     = (const float*)d_in[13];
    const float* out_w   = (const float*)d_in[14];
    const float* out_b   = (const float*)d_in[15];
    const float* ln2_g   = (const float*)d_in[16];
    const float* ln2_b   = (const float*)d_in[17];
    const float* fc_w    = (const float*)d_in[18];
    const float* fc_b    = (const float*)d_in[19];
    const float* proj_w  = (const float*)d_in[20];
    const float* proj_b  = (const float*)d_in[21];
    float* out = (float*)d_out;

    float* ln1   = symAddr(g_ln1);
    float* big   = symAddr(g_big);
    float* bigw  = symAddr(g_bigw);
    float* bigb  = symAddr(g_bigb);
    float* fcw   = symAddr(g_fcw);
    float* projw = symAddr(g_projw);
    float* outw  = symAddr(g_outw);
    float* jw    = symAddr(g_jw);
    float* rd    = symAddr(g_rd);
    float* gate  = symAddr(g_gate);
    float* pstd  = symAddr(g_pstd);
    float* pgeo  = symAddr(g_pgeo);
    float* comb  = symAddr(g_comb);
    float* res   = symAddr(g_res);
    float* mbuf  = symAddr(g_m);
    float* fcb   = symAddr(g_fc);

    // 1. pack weights (tf32) + biases; convert fc/proj/out weights
    pack_k<<<dim3((NB + 255) / 256, D), 256>>>(qkv_w, geov_w, w1w, w2w, w1r, w2r, gate_w,
                                               qkv_b, geov_b, gate_b, bigw, bigb);
    convw_k<<<(D * D4 + 255) / 256, 256>>>(fc_w, proj_w, out_w, fcw, projw, outw);

    // 2. ln1 (tf32-rounded; feeds mega-GEMM A)
    layernorm_k<<<T, 256>>>(x, ln1_g, ln1_b, ln1, 1);

    // 3. mega-GEMM: big = ln1 @ bigw + bigb
    gemm_pl_k<0><<<dim3((NB + 127) / 128, T / 128), 256>>>(ln1, D, bigw, NB, big, NB,
                                                           bigb, nullptr, T, NB, D, 0, 0);

    // 4. exterior + J6 + gate
    linesgate_k<<<(T * NH + 255) / 256, 256>>>(big, jw, rd, gate);

    // 5. merged std + geo flash attention
    flash_dual_k<<<dim3(T / 64, NH, 2), 128>>>(big, rd, jw, inc, pstd, pgeo);

    // 6. combine (rounded; feeds out-proj A)
    combine_k<<<(T * D + 255) / 256, 256>>>(pstd, pgeo, gate, comb);

    // 7. out proj + residual (res stays fp32)
    gemm_pl_k<1><<<dim3(D / 128, T / 64), 256>>>(comb, D, outw, D, res, D,
                                                 out_b, x, T, D, D, 0, 0);

    // 8. ln2 (rounded; feeds fc A)
    layernorm_k<<<T, 256>>>(res, ln2_g, ln2_b, mbuf, 1);

    // 9. fc + gelu (rounded output; feeds proj A)
    gemm_pl_k<0><<<dim3(D4 / 128, T / 128), 256>>>(mbuf, D, fcw, D4, fcb, D4,
                                                   fc_b, nullptr, T, D4, D, 1, 1);

    // 10. proj + bias + residual -> out (fp32)
    gemm_pl_k<1><<<dim3(D / 128, T / 64), 256>>>(fcb, D4, projw, D, out, D,
                                                 proj_b, res, T, D, D4, 0, 0);
}